// round 14
// baseline (speedup 1.0000x reference)
#include <cuda_runtime.h>
#include <cuda_fp16.h>
#include <cstdint>

// LSTMCell fused, two kernels:
//  1) convert_kernel: fp32 -> fp16 of X,H,W,U into scratch (GEMM tile layout).
//     2048 blocks x 256 thr, 8 rows per block, 8 LDG.128 in flight (MLP-8).
//  2) lstm_hmma_kernel: fp16 mma.sync GEMM, fp32 accumulate, cp.async 3-stage
//     ring, 2 CTAs/SM, fused LSTM epilogue.  (== best-known R10 geometry:
//     CTA 128x128, warp tile 64x32, JIT fragments)
// B=4096, I=H=1024.

#define HID     1024
#define BATCHSZ 4096
#define NCHUNK  32          // 2048 / 64
#define THREADS 256
#define STAGES  3

#define A_STAGE_BYTES (128*128)                 // 16 KB (128 rows x 64 fp16)
#define B_STAGE_BYTES (128*128)                 // 16 KB
#define STAGE_BYTES   (A_STAGE_BYTES + B_STAGE_BYTES)   // 32 KB
#define DYN_BYTES     (STAGES*STAGE_BYTES + 1024)       // 97 KB -> 2 CTAs/SM

// Scratch: 16384 rows x 2048 B (fp16).
// rows [0,4096): X | [4096,8192): H
// rows [8192,16384): 8192 + seg*4096 + gate*1024 + h   (seg 0 = W, 1 = U)
__device__ __align__(128) unsigned char g_scr[(size_t)16384 * 2048];

struct GateParams { const float* w[4]; const float* u[4]; const float* b[4]; };

static __device__ __forceinline__ uint32_t smem_u32(const void* p) {
    uint32_t a;
    asm("{ .reg .u64 t; cvta.to.shared.u64 t, %1; cvt.u32.u64 %0, t; }" : "=r"(a) : "l"(p));
    return a;
}
static __device__ __forceinline__ uint32_t sw128(uint32_t off) {
    return off ^ ((off >> 3) & 0x70);
}
static __device__ __forceinline__ void ldsm_x4(uint32_t* r, uint32_t addr) {
    asm volatile("ldmatrix.sync.aligned.m8n8.x4.shared.b16 {%0,%1,%2,%3}, [%4];"
        : "=r"(r[0]), "=r"(r[1]), "=r"(r[2]), "=r"(r[3]) : "r"(addr));
}
static __device__ __forceinline__ void mma_f16(float* c, const uint32_t* a, const uint32_t* b) {
    asm volatile("mma.sync.aligned.m16n8k16.row.col.f32.f16.f16.f32 "
        "{%0,%1,%2,%3}, {%4,%5,%6,%7}, {%8,%9}, {%0,%1,%2,%3};"
        : "+f"(c[0]), "+f"(c[1]), "+f"(c[2]), "+f"(c[3])
        : "r"(a[0]), "r"(a[1]), "r"(a[2]), "r"(a[3]), "r"(b[0]), "r"(b[1]));
}
#define CP_ASYNC16(dst, src) asm volatile("cp.async.cg.shared.global [%0], [%1], 16;" :: "r"(dst), "l"(src))
#define CP_COMMIT()          asm volatile("cp.async.commit_group;" ::: "memory")
#define CP_WAIT(n)           asm volatile("cp.async.wait_group %0;" :: "n"(n) : "memory")

static __device__ __forceinline__ float fast_sig(float x)  { return 1.0f / (1.0f + __expf(-x)); }
static __device__ __forceinline__ float fast_tanh(float x) { float e = __expf(2.0f * x); return 1.0f - 2.0f / (e + 1.0f); }

// ---- pre-pass: 2048 blocks x 256 thr; 8 rows per block, all 8 LDGs in flight
__global__ __launch_bounds__(256)
void convert_kernel(const float* __restrict__ X, const float* __restrict__ Hs, GateParams gp)
{
    const int t = threadIdx.x;

    float4 v[8];
    int rows[8];
    #pragma unroll
    for (int i = 0; i < 8; i++) {
        int row = blockIdx.x * 8 + i;
        rows[i] = row;
        const float* src;
        if (row < 4096)       src = X  + (size_t)row * 1024;
        else if (row < 8192)  src = Hs + (size_t)(row - 4096) * 1024;
        else {
            int r2  = row - 8192;
            int seg = r2 >> 12;
            int g   = (r2 >> 10) & 3;
            int hh  = r2 & 1023;
            src = (seg ? gp.u[g] : gp.w[g]) + (size_t)hh * 1024;
        }
        v[i] = *reinterpret_cast<const float4*>(src + t * 4);
    }
    #pragma unroll
    for (int i = 0; i < 8; i++) {
        __half2 p01 = __floats2half2_rn(v[i].x, v[i].y);
        __half2 p23 = __floats2half2_rn(v[i].z, v[i].w);
        unsigned char* dst = g_scr + (size_t)rows[i] * 2048;
        *reinterpret_cast<uint2*>(dst + (t >> 4) * 128 + (t & 15) * 8) =
            make_uint2(*reinterpret_cast<uint32_t*>(&p01),
                       *reinterpret_cast<uint32_t*>(&p23));
    }
}

__global__ __launch_bounds__(THREADS, 2)
void lstm_hmma_kernel(const float* __restrict__ oldc, GateParams gp,
                      float* __restrict__ outh, float* __restrict__ outc)
{
    extern __shared__ char dyn_raw[];
    char* dyn = (char*)(((uintptr_t)dyn_raw + 1023) & ~(uintptr_t)1023);
    __shared__ float bias_sm[128];

    const int tid  = threadIdx.x;
    const int lane = tid & 31;
    const int warp = tid >> 5;
    const int wm   = warp >> 2;          // 0..1 : 64 m-rows each
    const int wn   = warp & 3;           // 0..3 : 32 n-cols each
    const int h0   = blockIdx.x * 32;    // 32 h-tiles of 32
    const int m0   = blockIdx.y * 128;   // 32 m-tiles

    if (tid < 128) bias_sm[tid] = gp.b[tid >> 5][h0 + (tid & 31)];

    const int colf4  = tid & 7;     // 16B block within 128B row
    const int rowgrp = tid >> 3;    // 0..31; handles rows rowgrp+32i

    const uint32_t sm_base = smem_u32(dyn);
    const uint32_t arow_b = (uint32_t)((wm * 64 + (lane & 15)) * 128) + ((lane >> 4) << 4);
    const uint32_t brow_b = (uint32_t)((wn * 32 + ((lane >> 4) << 3) + (lane & 7)) * 128) + (((lane >> 3) & 1) << 4);

    uint32_t tdst[4];
    #pragma unroll
    for (int i = 0; i < 4; i++)
        tdst[i] = sw128((uint32_t)((rowgrp + 32 * i) * 128 + colf4 * 16));

    // B tile rows: n = gate*32 + hh; row rowgrp+32i -> gate i, hh = rowgrp.
    auto issue_chunk = [&](int c, uint32_t bufsm) {
        const int seg = c >> 4;
        const int kc  = c & 15;
        const unsigned char* abase = g_scr + ((size_t)(seg * 4096 + m0 + rowgrp)) * 2048 + kc * 128 + colf4 * 16;
        const unsigned char* bbase = g_scr + ((size_t)(8192 + seg * 4096 + h0 + rowgrp)) * 2048 + kc * 128 + colf4 * 16;
        #pragma unroll
        for (int i = 0; i < 4; i++) {
            CP_ASYNC16(bufsm + tdst[i], abase + (size_t)i * 32 * 2048);
            CP_ASYNC16(bufsm + A_STAGE_BYTES + tdst[i], bbase + (size_t)i * 1024 * 2048);
        }
    };

    float acc[4][4][4];
    #pragma unroll
    for (int mt = 0; mt < 4; mt++)
        #pragma unroll
        for (int nt = 0; nt < 4; nt++)
            #pragma unroll
            for (int q = 0; q < 4; q++) acc[mt][nt][q] = 0.0f;

    #pragma unroll
    for (int p = 0; p < STAGES - 1; p++) {
        issue_chunk(p, sm_base + p * STAGE_BYTES);
        CP_COMMIT();
    }
    CP_WAIT(STAGES - 2);
    __syncthreads();

    int buf = 0;
    for (int c = 0; c < NCHUNK; c++) {
        int nc2 = c + STAGES - 1;
        if (nc2 < NCHUNK) {
            int nb = buf + STAGES - 1; if (nb >= STAGES) nb -= STAGES;
            issue_chunk(nc2, sm_base + nb * STAGE_BYTES);
        }
        CP_COMMIT();

        // compute 64-K chunk: 4 k16 steps (JIT fragments — proven fastest)
        {
            const uint32_t stA = sm_base + buf * STAGE_BYTES;
            const uint32_t stB = stA + A_STAGE_BYTES;
            #pragma unroll
            for (int ks = 0; ks < 4; ks++) {
                uint32_t ah[4][4], bb[4][2];
                #pragma unroll
                for (int mt = 0; mt < 4; mt++)
                    ldsm_x4(ah[mt], stA + sw128(arow_b + (uint32_t)(mt * 2048 + ks * 32)));
                #pragma unroll
                for (int nt2 = 0; nt2 < 2; nt2++) {
                    uint32_t r[4];
                    ldsm_x4(r, stB + sw128(brow_b + (uint32_t)(nt2 * 2048 + ks * 32)));
                    bb[nt2*2][0] = r[0]; bb[nt2*2][1] = r[1];
                    bb[nt2*2+1][0] = r[2]; bb[nt2*2+1][1] = r[3];
                }
                #pragma unroll
                for (int mt = 0; mt < 4; mt++)
                    #pragma unroll
                    for (int nt = 0; nt < 4; nt++)
                        mma_f16(acc[mt][nt], ah[mt], bb[nt]);
            }
        }

        CP_WAIT(STAGES - 2);
        __syncthreads();
        if (++buf == STAGES) buf = 0;
    }

    // ---- epilogue: accs -> smem transpose [n][m], then fused LSTM ----
    float* Csm = reinterpret_cast<float*>(dyn);   // [128][129] floats (66 KB < 97 KB)
    {
        const int gid = lane >> 2;
        const int tig = lane & 3;
        #pragma unroll
        for (int mt = 0; mt < 4; mt++)
            #pragma unroll
            for (int nt = 0; nt < 4; nt++) {
                int row = wm * 64 + mt * 16 + gid;
                int col = wn * 32 + nt * 8 + tig * 2;
                Csm[(col    ) * 129 + row    ] = acc[mt][nt][0];
                Csm[(col + 1) * 129 + row    ] = acc[mt][nt][1];
                Csm[(col    ) * 129 + row + 8] = acc[mt][nt][2];
                Csm[(col + 1) * 129 + row + 8] = acc[mt][nt][3];
            }
    }
    __syncthreads();

    #pragma unroll
    for (int it = 0; it < 16; it++) {
        int idx = tid + it * 256;           // 4096 = 128 m x 32 hh
        int hh = idx & 31;
        int m  = idx >> 5;
        float gi = Csm[( 0 + hh) * 129 + m] + bias_sm[ 0 + hh];
        float go = Csm[(32 + hh) * 129 + m] + bias_sm[32 + hh];
        float gf = Csm[(64 + hh) * 129 + m] + bias_sm[64 + hh];
        float gc = Csm[(96 + hh) * 129 + m] + bias_sm[96 + hh];
        size_t g = (size_t)(m0 + m) * 1024 + h0 + hh;
        float ig = fast_sig(gi);
        float og = fast_sig(go);
        float fg = fast_sig(gf);
        float ct = fast_tanh(gc);
        float nc = fg * oldc[g] + ig * ct;
        outh[g] = og * fast_tanh(nc);
        outc[g] = nc;
    }
}

extern "C" void kernel_launch(void* const* d_in, const int* in_sizes, int n_in,
                              void* d_out, int out_size)
{
    const float* incoming = (const float*)d_in[0];
    const float* old_h    = (const float*)d_in[1];
    const float* old_c    = (const float*)d_in[2];

    GateParams gp;
    gp.w[0] = (const float*)d_in[3];  gp.b[0] = (const float*)d_in[4];  gp.u[0] = (const float*)d_in[5];
    gp.w[1] = (const float*)d_in[6];  gp.b[1] = (const float*)d_in[7];  gp.u[1] = (const float*)d_in[8];
    gp.w[2] = (const float*)d_in[9];  gp.b[2] = (const float*)d_in[10]; gp.u[2] = (const float*)d_in[11];
    gp.w[3] = (const float*)d_in[12]; gp.b[3] = (const float*)d_in[13]; gp.u[3] = (const float*)d_in[14];

    float* out_h = (float*)d_out;
    float* out_c = out_h + (size_t)BATCHSZ * HID;

    convert_kernel<<<2048, 256>>>(incoming, old_h, gp);

    cudaFuncSetAttribute(lstm_hmma_kernel, cudaFuncAttributeMaxDynamicSharedMemorySize, DYN_BYTES);
    dim3 grid(HID / 32, BATCHSZ / 128);   // 32 x 32 = 1024 CTAs
    lstm_hmma_kernel<<<grid, THREADS, DYN_BYTES>>>(old_c, gp, out_h, out_c);
}

// round 15
// speedup vs baseline: 1.4687x; 1.4687x over previous
#include <cuda_runtime.h>
#include <cuda_fp16.h>
#include <cstdint>

// LSTMCell fused, two kernels (byte-for-byte the banked 209.7us R10 artifact):
//  1) convert_kernel: fp32 -> fp16 of X,H,W,U into scratch (GEMM tile layout).
//     MLP-8: 1024 blocks x 256 thr, 16 rows/block in two 8-row batches.
//  2) lstm_hmma_kernel: fp16 mma.sync GEMM, fp32 accumulate, cp.async 3-stage
//     ring, 2 CTAs/SM, fused LSTM epilogue. CTA 128x128, warp tile 64x32.
// B=4096, I=H=1024.

#define HID     1024
#define BATCHSZ 4096
#define NCHUNK  32          // 2048 / 64
#define THREADS 256
#define STAGES  3

#define A_STAGE_BYTES (128*128)                 // 16 KB (128 rows x 64 fp16)
#define B_STAGE_BYTES (128*128)                 // 16 KB
#define STAGE_BYTES   (A_STAGE_BYTES + B_STAGE_BYTES)   // 32 KB
#define DYN_BYTES     (STAGES*STAGE_BYTES + 1024)       // 97 KB -> 2 CTAs/SM

// Scratch: 16384 rows x 2048 B (fp16).
// rows [0,4096): X | [4096,8192): H
// rows [8192,16384): 8192 + seg*4096 + gate*1024 + h   (seg 0 = W, 1 = U)
__device__ __align__(128) unsigned char g_scr[(size_t)16384 * 2048];

struct GateParams { const float* w[4]; const float* u[4]; const float* b[4]; };

static __device__ __forceinline__ uint32_t smem_u32(const void* p) {
    uint32_t a;
    asm("{ .reg .u64 t; cvta.to.shared.u64 t, %1; cvt.u32.u64 %0, t; }" : "=r"(a) : "l"(p));
    return a;
}
static __device__ __forceinline__ uint32_t sw128(uint32_t off) {
    return off ^ ((off >> 3) & 0x70);
}
static __device__ __forceinline__ void ldsm_x4(uint32_t* r, uint32_t addr) {
    asm volatile("ldmatrix.sync.aligned.m8n8.x4.shared.b16 {%0,%1,%2,%3}, [%4];"
        : "=r"(r[0]), "=r"(r[1]), "=r"(r[2]), "=r"(r[3]) : "r"(addr));
}
static __device__ __forceinline__ void mma_f16(float* c, const uint32_t* a, const uint32_t* b) {
    asm volatile("mma.sync.aligned.m16n8k16.row.col.f32.f16.f16.f32 "
        "{%0,%1,%2,%3}, {%4,%5,%6,%7}, {%8,%9}, {%0,%1,%2,%3};"
        : "+f"(c[0]), "+f"(c[1]), "+f"(c[2]), "+f"(c[3])
        : "r"(a[0]), "r"(a[1]), "r"(a[2]), "r"(a[3]), "r"(b[0]), "r"(b[1]));
}
#define CP_ASYNC16(dst, src) asm volatile("cp.async.cg.shared.global [%0], [%1], 16;" :: "r"(dst), "l"(src))
#define CP_COMMIT()          asm volatile("cp.async.commit_group;" ::: "memory")
#define CP_WAIT(n)           asm volatile("cp.async.wait_group %0;" :: "n"(n) : "memory")

static __device__ __forceinline__ float fast_sig(float x)  { return 1.0f / (1.0f + __expf(-x)); }
static __device__ __forceinline__ float fast_tanh(float x) { float e = __expf(2.0f * x); return 1.0f - 2.0f / (e + 1.0f); }

// ---- pre-pass: 1024 blocks x 256 thr; 16 rows per block, 8 rows per batch
__global__ __launch_bounds__(256)
void convert_kernel(const float* __restrict__ X, const float* __restrict__ Hs, GateParams gp)
{
    const int t = threadIdx.x;

    #pragma unroll
    for (int b = 0; b < 2; b++) {
        float4 v[8];
        int rows[8];
        #pragma unroll
        for (int i = 0; i < 8; i++) {
            int row = blockIdx.x * 16 + b * 8 + i;
            rows[i] = row;
            const float* src;
            if (row < 4096)       src = X  + (size_t)row * 1024;
            else if (row < 8192)  src = Hs + (size_t)(row - 4096) * 1024;
            else {
                int r2  = row - 8192;
                int seg = r2 >> 12;
                int g   = (r2 >> 10) & 3;
                int hh  = r2 & 1023;
                src = (seg ? gp.u[g] : gp.w[g]) + (size_t)hh * 1024;
            }
            v[i] = *reinterpret_cast<const float4*>(src + t * 4);
        }
        #pragma unroll
        for (int i = 0; i < 8; i++) {
            __half2 p01 = __floats2half2_rn(v[i].x, v[i].y);
            __half2 p23 = __floats2half2_rn(v[i].z, v[i].w);
            unsigned char* dst = g_scr + (size_t)rows[i] * 2048;
            *reinterpret_cast<uint2*>(dst + (t >> 4) * 128 + (t & 15) * 8) =
                make_uint2(*reinterpret_cast<uint32_t*>(&p01),
                           *reinterpret_cast<uint32_t*>(&p23));
        }
    }
}

__global__ __launch_bounds__(THREADS, 2)
void lstm_hmma_kernel(const float* __restrict__ oldc, GateParams gp,
                      float* __restrict__ outh, float* __restrict__ outc)
{
    extern __shared__ char dyn_raw[];
    char* dyn = (char*)(((uintptr_t)dyn_raw + 1023) & ~(uintptr_t)1023);
    __shared__ float bias_sm[128];

    const int tid  = threadIdx.x;
    const int lane = tid & 31;
    const int warp = tid >> 5;
    const int wm   = warp >> 2;          // 0..1 : 64 m-rows each
    const int wn   = warp & 3;           // 0..3 : 32 n-cols each
    const int h0   = blockIdx.x * 32;    // 32 h-tiles of 32
    const int m0   = blockIdx.y * 128;   // 32 m-tiles

    if (tid < 128) bias_sm[tid] = gp.b[tid >> 5][h0 + (tid & 31)];

    const int colf4  = tid & 7;     // 16B block within 128B row
    const int rowgrp = tid >> 3;    // 0..31; handles rows rowgrp+32i

    const uint32_t sm_base = smem_u32(dyn);
    const uint32_t arow_b = (uint32_t)((wm * 64 + (lane & 15)) * 128) + ((lane >> 4) << 4);
    const uint32_t brow_b = (uint32_t)((wn * 32 + ((lane >> 4) << 3) + (lane & 7)) * 128) + (((lane >> 3) & 1) << 4);

    uint32_t tdst[4];
    #pragma unroll
    for (int i = 0; i < 4; i++)
        tdst[i] = sw128((uint32_t)((rowgrp + 32 * i) * 128 + colf4 * 16));

    // B tile rows: n = gate*32 + hh; row rowgrp+32i -> gate i, hh = rowgrp.
    auto issue_chunk = [&](int c, uint32_t bufsm) {
        const int seg = c >> 4;
        const int kc  = c & 15;
        const unsigned char* abase = g_scr + ((size_t)(seg * 4096 + m0 + rowgrp)) * 2048 + kc * 128 + colf4 * 16;
        const unsigned char* bbase = g_scr + ((size_t)(8192 + seg * 4096 + h0 + rowgrp)) * 2048 + kc * 128 + colf4 * 16;
        #pragma unroll
        for (int i = 0; i < 4; i++) {
            CP_ASYNC16(bufsm + tdst[i], abase + (size_t)i * 32 * 2048);
            CP_ASYNC16(bufsm + A_STAGE_BYTES + tdst[i], bbase + (size_t)i * 1024 * 2048);
        }
    };

    float acc[4][4][4];
    #pragma unroll
    for (int mt = 0; mt < 4; mt++)
        #pragma unroll
        for (int nt = 0; nt < 4; nt++)
            #pragma unroll
            for (int q = 0; q < 4; q++) acc[mt][nt][q] = 0.0f;

    #pragma unroll
    for (int p = 0; p < STAGES - 1; p++) {
        issue_chunk(p, sm_base + p * STAGE_BYTES);
        CP_COMMIT();
    }
    CP_WAIT(STAGES - 2);
    __syncthreads();

    int buf = 0;
    for (int c = 0; c < NCHUNK; c++) {
        int nc2 = c + STAGES - 1;
        if (nc2 < NCHUNK) {
            int nb = buf + STAGES - 1; if (nb >= STAGES) nb -= STAGES;
            issue_chunk(nc2, sm_base + nb * STAGE_BYTES);
        }
        CP_COMMIT();

        // compute 64-K chunk: 4 k16 steps (JIT fragments — proven fastest)
        {
            const uint32_t stA = sm_base + buf * STAGE_BYTES;
            const uint32_t stB = stA + A_STAGE_BYTES;
            #pragma unroll
            for (int ks = 0; ks < 4; ks++) {
                uint32_t ah[4][4], bb[4][2];
                #pragma unroll
                for (int mt = 0; mt < 4; mt++)
                    ldsm_x4(ah[mt], stA + sw128(arow_b + (uint32_t)(mt * 2048 + ks * 32)));
                #pragma unroll
                for (int nt2 = 0; nt2 < 2; nt2++) {
                    uint32_t r[4];
                    ldsm_x4(r, stB + sw128(brow_b + (uint32_t)(nt2 * 2048 + ks * 32)));
                    bb[nt2*2][0] = r[0]; bb[nt2*2][1] = r[1];
                    bb[nt2*2+1][0] = r[2]; bb[nt2*2+1][1] = r[3];
                }
                #pragma unroll
                for (int mt = 0; mt < 4; mt++)
                    #pragma unroll
                    for (int nt = 0; nt < 4; nt++)
                        mma_f16(acc[mt][nt], ah[mt], bb[nt]);
            }
        }

        CP_WAIT(STAGES - 2);
        __syncthreads();
        if (++buf == STAGES) buf = 0;
    }

    // ---- epilogue: accs -> smem transpose [n][m], then fused LSTM ----
    float* Csm = reinterpret_cast<float*>(dyn);   // [128][129] floats (66 KB < 97 KB)
    {
        const int gid = lane >> 2;
        const int tig = lane & 3;
        #pragma unroll
        for (int mt = 0; mt < 4; mt++)
            #pragma unroll
            for (int nt = 0; nt < 4; nt++) {
                int row = wm * 64 + mt * 16 + gid;
                int col = wn * 32 + nt * 8 + tig * 2;
                Csm[(col    ) * 129 + row    ] = acc[mt][nt][0];
                Csm[(col + 1) * 129 + row    ] = acc[mt][nt][1];
                Csm[(col    ) * 129 + row + 8] = acc[mt][nt][2];
                Csm[(col + 1) * 129 + row + 8] = acc[mt][nt][3];
            }
    }
    __syncthreads();

    #pragma unroll
    for (int it = 0; it < 16; it++) {
        int idx = tid + it * 256;           // 4096 = 128 m x 32 hh
        int hh = idx & 31;
        int m  = idx >> 5;
        float gi = Csm[( 0 + hh) * 129 + m] + bias_sm[ 0 + hh];
        float go = Csm[(32 + hh) * 129 + m] + bias_sm[32 + hh];
        float gf = Csm[(64 + hh) * 129 + m] + bias_sm[64 + hh];
        float gc = Csm[(96 + hh) * 129 + m] + bias_sm[96 + hh];
        size_t g = (size_t)(m0 + m) * 1024 + h0 + hh;
        float ig = fast_sig(gi);
        float og = fast_sig(go);
        float fg = fast_sig(gf);
        float ct = fast_tanh(gc);
        float nc = fg * oldc[g] + ig * ct;
        outh[g] = og * fast_tanh(nc);
        outc[g] = nc;
    }
}

extern "C" void kernel_launch(void* const* d_in, const int* in_sizes, int n_in,
                              void* d_out, int out_size)
{
    const float* incoming = (const float*)d_in[0];
    const float* old_h    = (const float*)d_in[1];
    const float* old_c    = (const float*)d_in[2];

    GateParams gp;
    gp.w[0] = (const float*)d_in[3];  gp.b[0] = (const float*)d_in[4];  gp.u[0] = (const float*)d_in[5];
    gp.w[1] = (const float*)d_in[6];  gp.b[1] = (const float*)d_in[7];  gp.u[1] = (const float*)d_in[8];
    gp.w[2] = (const float*)d_in[9];  gp.b[2] = (const float*)d_in[10]; gp.u[2] = (const float*)d_in[11];
    gp.w[3] = (const float*)d_in[12]; gp.b[3] = (const float*)d_in[13]; gp.u[3] = (const float*)d_in[14];

    float* out_h = (float*)d_out;
    float* out_c = out_h + (size_t)BATCHSZ * HID;

    convert_kernel<<<1024, 256>>>(incoming, old_h, gp);

    cudaFuncSetAttribute(lstm_hmma_kernel, cudaFuncAttributeMaxDynamicSharedMemorySize, DYN_BYTES);
    dim3 grid(HID / 32, BATCHSZ / 128);   // 32 x 32 = 1024 CTAs
    lstm_hmma_kernel<<<grid, THREADS, DYN_BYTES>>>(old_c, gp, out_h, out_c);
}

// round 17
// speedup vs baseline: 1.4784x; 1.0066x over previous
#include <cuda_runtime.h>
#include <cuda_fp16.h>
#include <cstdint>

// LSTMCell fused, two kernels:
//  1) convert_kernel: fp32 -> fp16 of X,H,W,U into scratch (GEMM tile layout).
//     2048 blocks x 256 thr, 8 rows per block, all 8 LDG.128 in flight.
//  2) lstm_hmma_kernel: fp16 mma.sync GEMM, fp32 accumulate, cp.async 3-stage
//     ring, 2 CTAs/SM, fused LSTM epilogue. CTA 128x128, warp tile 64x32.
//     (byte-identical to the 209.7us best-known artifact)
// B=4096, I=H=1024.

#define HID     1024
#define BATCHSZ 4096
#define NCHUNK  32          // 2048 / 64
#define THREADS 256
#define STAGES  3

#define A_STAGE_BYTES (128*128)                 // 16 KB (128 rows x 64 fp16)
#define B_STAGE_BYTES (128*128)                 // 16 KB
#define STAGE_BYTES   (A_STAGE_BYTES + B_STAGE_BYTES)   // 32 KB
#define DYN_BYTES     (STAGES*STAGE_BYTES + 1024)       // 97 KB -> 2 CTAs/SM

// Scratch: 16384 rows x 2048 B (fp16).
// rows [0,4096): X | [4096,8192): H
// rows [8192,16384): 8192 + seg*4096 + gate*1024 + h   (seg 0 = W, 1 = U)
__device__ __align__(128) unsigned char g_scr[(size_t)16384 * 2048];

struct GateParams { const float* w[4]; const float* u[4]; const float* b[4]; };

static __device__ __forceinline__ uint32_t smem_u32(const void* p) {
    uint32_t a;
    asm("{ .reg .u64 t; cvta.to.shared.u64 t, %1; cvt.u32.u64 %0, t; }" : "=r"(a) : "l"(p));
    return a;
}
static __device__ __forceinline__ uint32_t sw128(uint32_t off) {
    return off ^ ((off >> 3) & 0x70);
}
static __device__ __forceinline__ void ldsm_x4(uint32_t* r, uint32_t addr) {
    asm volatile("ldmatrix.sync.aligned.m8n8.x4.shared.b16 {%0,%1,%2,%3}, [%4];"
        : "=r"(r[0]), "=r"(r[1]), "=r"(r[2]), "=r"(r[3]) : "r"(addr));
}
static __device__ __forceinline__ void mma_f16(float* c, const uint32_t* a, const uint32_t* b) {
    asm volatile("mma.sync.aligned.m16n8k16.row.col.f32.f16.f16.f32 "
        "{%0,%1,%2,%3}, {%4,%5,%6,%7}, {%8,%9}, {%0,%1,%2,%3};"
        : "+f"(c[0]), "+f"(c[1]), "+f"(c[2]), "+f"(c[3])
        : "r"(a[0]), "r"(a[1]), "r"(a[2]), "r"(a[3]), "r"(b[0]), "r"(b[1]));
}
#define CP_ASYNC16(dst, src) asm volatile("cp.async.cg.shared.global [%0], [%1], 16;" :: "r"(dst), "l"(src))
#define CP_COMMIT()          asm volatile("cp.async.commit_group;" ::: "memory")
#define CP_WAIT(n)           asm volatile("cp.async.wait_group %0;" :: "n"(n) : "memory")

static __device__ __forceinline__ float fast_sig(float x)  { return 1.0f / (1.0f + __expf(-x)); }
static __device__ __forceinline__ float fast_tanh(float x) { float e = __expf(2.0f * x); return 1.0f - 2.0f / (e + 1.0f); }

// ---- pre-pass: 2048 blocks x 256 thr; 8 rows per block, all 8 LDGs in flight
__global__ __launch_bounds__(256)
void convert_kernel(const float* __restrict__ X, const float* __restrict__ Hs, GateParams gp)
{
    const int t = threadIdx.x;

    float4 v[8];
    int rows[8];
    #pragma unroll
    for (int i = 0; i < 8; i++) {
        int row = blockIdx.x * 8 + i;
        rows[i] = row;
        const float* src;
        if (row < 4096)       src = X  + (size_t)row * 1024;
        else if (row < 8192)  src = Hs + (size_t)(row - 4096) * 1024;
        else {
            int r2  = row - 8192;
            int seg = r2 >> 12;
            int g   = (r2 >> 10) & 3;
            int hh  = r2 & 1023;
            src = (seg ? gp.u[g] : gp.w[g]) + (size_t)hh * 1024;
        }
        v[i] = *reinterpret_cast<const float4*>(src + t * 4);
    }
    #pragma unroll
    for (int i = 0; i < 8; i++) {
        __half2 p01 = __floats2half2_rn(v[i].x, v[i].y);
        __half2 p23 = __floats2half2_rn(v[i].z, v[i].w);
        unsigned char* dst = g_scr + (size_t)rows[i] * 2048;
        *reinterpret_cast<uint2*>(dst + (t >> 4) * 128 + (t & 15) * 8) =
            make_uint2(*reinterpret_cast<uint32_t*>(&p01),
                       *reinterpret_cast<uint32_t*>(&p23));
    }
}

__global__ __launch_bounds__(THREADS, 2)
void lstm_hmma_kernel(const float* __restrict__ oldc, GateParams gp,
                      float* __restrict__ outh, float* __restrict__ outc)
{
    extern __shared__ char dyn_raw[];
    char* dyn = (char*)(((uintptr_t)dyn_raw + 1023) & ~(uintptr_t)1023);
    __shared__ float bias_sm[128];

    const int tid  = threadIdx.x;
    const int lane = tid & 31;
    const int warp = tid >> 5;
    const int wm   = warp >> 2;          // 0..1 : 64 m-rows each
    const int wn   = warp & 3;           // 0..3 : 32 n-cols each
    const int h0   = blockIdx.x * 32;    // 32 h-tiles of 32
    const int m0   = blockIdx.y * 128;   // 32 m-tiles

    if (tid < 128) bias_sm[tid] = gp.b[tid >> 5][h0 + (tid & 31)];

    const int colf4  = tid & 7;     // 16B block within 128B row
    const int rowgrp = tid >> 3;    // 0..31; handles rows rowgrp+32i

    const uint32_t sm_base = smem_u32(dyn);
    const uint32_t arow_b = (uint32_t)((wm * 64 + (lane & 15)) * 128) + ((lane >> 4) << 4);
    const uint32_t brow_b = (uint32_t)((wn * 32 + ((lane >> 4) << 3) + (lane & 7)) * 128) + (((lane >> 3) & 1) << 4);

    uint32_t tdst[4];
    #pragma unroll
    for (int i = 0; i < 4; i++)
        tdst[i] = sw128((uint32_t)((rowgrp + 32 * i) * 128 + colf4 * 16));

    // B tile rows: n = gate*32 + hh; row rowgrp+32i -> gate i, hh = rowgrp.
    auto issue_chunk = [&](int c, uint32_t bufsm) {
        const int seg = c >> 4;
        const int kc  = c & 15;
        const unsigned char* abase = g_scr + ((size_t)(seg * 4096 + m0 + rowgrp)) * 2048 + kc * 128 + colf4 * 16;
        const unsigned char* bbase = g_scr + ((size_t)(8192 + seg * 4096 + h0 + rowgrp)) * 2048 + kc * 128 + colf4 * 16;
        #pragma unroll
        for (int i = 0; i < 4; i++) {
            CP_ASYNC16(bufsm + tdst[i], abase + (size_t)i * 32 * 2048);
            CP_ASYNC16(bufsm + A_STAGE_BYTES + tdst[i], bbase + (size_t)i * 1024 * 2048);
        }
    };

    float acc[4][4][4];
    #pragma unroll
    for (int mt = 0; mt < 4; mt++)
        #pragma unroll
        for (int nt = 0; nt < 4; nt++)
            #pragma unroll
            for (int q = 0; q < 4; q++) acc[mt][nt][q] = 0.0f;

    #pragma unroll
    for (int p = 0; p < STAGES - 1; p++) {
        issue_chunk(p, sm_base + p * STAGE_BYTES);
        CP_COMMIT();
    }
    CP_WAIT(STAGES - 2);
    __syncthreads();

    int buf = 0;
    for (int c = 0; c < NCHUNK; c++) {
        int nc2 = c + STAGES - 1;
        if (nc2 < NCHUNK) {
            int nb = buf + STAGES - 1; if (nb >= STAGES) nb -= STAGES;
            issue_chunk(nc2, sm_base + nb * STAGE_BYTES);
        }
        CP_COMMIT();

        // compute 64-K chunk: 4 k16 steps (JIT fragments — proven fastest)
        {
            const uint32_t stA = sm_base + buf * STAGE_BYTES;
            const uint32_t stB = stA + A_STAGE_BYTES;
            #pragma unroll
            for (int ks = 0; ks < 4; ks++) {
                uint32_t ah[4][4], bb[4][2];
                #pragma unroll
                for (int mt = 0; mt < 4; mt++)
                    ldsm_x4(ah[mt], stA + sw128(arow_b + (uint32_t)(mt * 2048 + ks * 32)));
                #pragma unroll
                for (int nt2 = 0; nt2 < 2; nt2++) {
                    uint32_t r[4];
                    ldsm_x4(r, stB + sw128(brow_b + (uint32_t)(nt2 * 2048 + ks * 32)));
                    bb[nt2*2][0] = r[0]; bb[nt2*2][1] = r[1];
                    bb[nt2*2+1][0] = r[2]; bb[nt2*2+1][1] = r[3];
                }
                #pragma unroll
                for (int mt = 0; mt < 4; mt++)
                    #pragma unroll
                    for (int nt = 0; nt < 4; nt++)
                        mma_f16(acc[mt][nt], ah[mt], bb[nt]);
            }
        }

        CP_WAIT(STAGES - 2);
        __syncthreads();
        if (++buf == STAGES) buf = 0;
    }

    // ---- epilogue: accs -> smem transpose [n][m], then fused LSTM ----
    float* Csm = reinterpret_cast<float*>(dyn);   // [128][129] floats (66 KB < 97 KB)
    {
        const int gid = lane >> 2;
        const int tig = lane & 3;
        #pragma unroll
        for (int mt = 0; mt < 4; mt++)
            #pragma unroll
            for (int nt = 0; nt < 4; nt++) {
                int row = wm * 64 + mt * 16 + gid;
                int col = wn * 32 + nt * 8 + tig * 2;
                Csm[(col    ) * 129 + row    ] = acc[mt][nt][0];
                Csm[(col + 1) * 129 + row    ] = acc[mt][nt][1];
                Csm[(col    ) * 129 + row + 8] = acc[mt][nt][2];
                Csm[(col + 1) * 129 + row + 8] = acc[mt][nt][3];
            }
    }
    __syncthreads();

    #pragma unroll
    for (int it = 0; it < 16; it++) {
        int idx = tid + it * 256;           // 4096 = 128 m x 32 hh
        int hh = idx & 31;
        int m  = idx >> 5;
        float gi = Csm[( 0 + hh) * 129 + m] + bias_sm[ 0 + hh];
        float go = Csm[(32 + hh) * 129 + m] + bias_sm[32 + hh];
        float gf = Csm[(64 + hh) * 129 + m] + bias_sm[64 + hh];
        float gc = Csm[(96 + hh) * 129 + m] + bias_sm[96 + hh];
        size_t g = (size_t)(m0 + m) * 1024 + h0 + hh;
        float ig = fast_sig(gi);
        float og = fast_sig(go);
        float fg = fast_sig(gf);
        float ct = fast_tanh(gc);
        float nc = fg * oldc[g] + ig * ct;
        outh[g] = og * fast_tanh(nc);
        outc[g] = nc;
    }
}

extern "C" void kernel_launch(void* const* d_in, const int* in_sizes, int n_in,
                              void* d_out, int out_size)
{
    const float* incoming = (const float*)d_in[0];
    const float* old_h    = (const float*)d_in[1];
    const float* old_c    = (const float*)d_in[2];

    GateParams gp;
    gp.w[0] = (const float*)d_in[3];  gp.b[0] = (const float*)d_in[4];  gp.u[0] = (const float*)d_in[5];
    gp.w[1] = (const float*)d_in[6];  gp.b[1] = (const float*)d_in[7];  gp.u[1] = (const float*)d_in[8];
    gp.w[2] = (const float*)d_in[9];  gp.b[2] = (const float*)d_in[10]; gp.u[2] = (const float*)d_in[11];
    gp.w[3] = (const float*)d_in[12]; gp.b[3] = (const float*)d_in[13]; gp.u[3] = (const float*)d_in[14];

    float* out_h = (float*)d_out;
    float* out_c = out_h + (size_t)BATCHSZ * HID;

    convert_kernel<<<2048, 256>>>(incoming, old_h, gp);

    cudaFuncSetAttribute(lstm_hmma_kernel, cudaFuncAttributeMaxDynamicSharedMemorySize, DYN_BYTES);
    dim3 grid(HID / 32, BATCHSZ / 128);   // 32 x 32 = 1024 CTAs
    lstm_hmma_kernel<<<grid, THREADS, DYN_BYTES>>>(old_c, gp, out_h, out_c);
}